// round 2
// baseline (speedup 1.0000x reference)
#include <cuda_runtime.h>
#include <cuda_bf16.h>

#define NPTS 8192
#define MAXN 128
#define TILE 4096          // 4096 pts * 3 floats * 4B = 48KB static SMEM
#define CUT2 0.015625f     // 0.125^2, exact in fp32
#define WARPS_PER_BLOCK 8
#define THREADS (WARPS_PER_BLOCK * 32)

__global__ void __launch_bounds__(THREADS)
neigh_kernel(const float* __restrict__ pos,
             float* __restrict__ out_idx,   // [NPTS, MAXN] as float32
             int* __restrict__ out_max)     // [1], float32 bits via int atomicMax
{
    __shared__ float sx[TILE];
    __shared__ float sy[TILE];
    __shared__ float sz[TILE];

    const int tid  = threadIdx.x;
    const int warp = tid >> 5;
    const int lane = tid & 31;
    const int row  = blockIdx.x * WARPS_PER_BLOCK + warp;

    // Broadcast this row's position (L2-resident, tiny)
    const float px = pos[row * 3 + 0];
    const float py = pos[row * 3 + 1];
    const float pz = pos[row * 3 + 2];

    int count = 0;  // warp-uniform running neighbor count (uncapped)

    for (int tile = 0; tile < NPTS; tile += TILE) {
        // Stage AoS -> SoA into shared
        for (int idx = tid; idx < TILE * 3; idx += THREADS) {
            const int p = idx / 3;
            const int c = idx - p * 3;
            const float v = pos[(tile + p) * 3 + c];
            if (c == 0)      sx[p] = v;
            else if (c == 1) sy[p] = v;
            else             sz[p] = v;
        }
        __syncthreads();

        #pragma unroll 4
        for (int j0 = 0; j0 < TILE; j0 += 32) {
            const int j  = j0 + lane;
            const int jg = tile + j;
            // Exact left-to-right f32 arithmetic matching the JAX reference:
            // d2 = (dx*dx + dy*dy) + dz*dz, no FMA contraction.
            const float dx = __fsub_rn(sx[j], px);
            const float dy = __fsub_rn(sy[j], py);
            const float dz = __fsub_rn(sz[j], pz);
            const float d2 = __fadd_rn(__fadd_rn(__fmul_rn(dx, dx),
                                                 __fmul_rn(dy, dy)),
                                       __fmul_rn(dz, dz));
            const bool  in = (d2 <= CUT2) && (jg != row);
            const unsigned m = __ballot_sync(0xffffffffu, in);
            if (m) {
                const int prefix = __popc(m & ((1u << lane) - 1u));
                const int w = count + prefix;
                if (in && w < MAXN) out_idx[row * MAXN + w] = (float)jg;
                count += __popc(m);
            }
        }
        __syncthreads();
    }

    // Pad the rest of the row with -1.0f (MASK_VALUE as float32)
    const int start = count < MAXN ? count : MAXN;
    for (int k = start + lane; k < MAXN; k += 32) {
        out_idx[row * MAXN + k] = -1.0f;
    }

    // Global max of UNCAPPED per-row counts, stored as float32.
    // Non-negative IEEE floats order identically to their int bit patterns,
    // so integer atomicMax on the float bits is exact. Memset 0 == 0.0f.
    if (lane == 0) atomicMax(out_max, __float_as_int((float)count));
}

extern "C" void kernel_launch(void* const* d_in, const int* in_sizes, int n_in,
                              void* d_out, int out_size)
{
    const float* pos = (const float*)d_in[0];
    float* out = (float*)d_out;

    // Output layout: [to_idx (N*128)] [cell_indices (N*128*3)] [actual_max (1)]
    const size_t toidx_elems = (size_t)NPTS * MAXN;          // 1,048,576
    const size_t cell_elems  = (size_t)NPTS * MAXN * 3;      // 3,145,728

    // Zero cell_indices and the max slot (0x0 == 0.0f; graph-capturable)
    cudaMemsetAsync(out + toidx_elems, 0, (cell_elems + 1) * sizeof(float), 0);

    neigh_kernel<<<NPTS / WARPS_PER_BLOCK, THREADS>>>(
        pos, out, (int*)(out + toidx_elems + cell_elems));
}

// round 3
// speedup vs baseline: 2.5731x; 2.5731x over previous
#include <cuda_runtime.h>
#include <cuda_bf16.h>

#define NPTS 8192
#define MAXN 128
#define NC 8
#define NCELLS 512          // 8^3
#define CUT2 0.015625f      // 0.125^2, exact in fp32
#define WPB 8               // warps per block (main kernel)
#define TPB (WPB * 32)

// Scratch (no allocations allowed)
__device__ int    g_count[NCELLS];
__device__ int    g_cursor[NCELLS];
__device__ int    g_start[NCELLS + 1];
__device__ float4 g_spos[NPTS];      // cell-sorted {x,y,z, idx-as-float-bits}

__device__ __forceinline__ int cell_x(float v) {
    // v in [0,1): v*8 is exact (exponent shift), floor via trunc. Clamp for safety.
    int c = (int)(v * 8.0f);
    return c < 0 ? 0 : (c > 7 ? 7 : c);
}

__global__ void zero_kernel() {
    g_count[threadIdx.x] = 0;
}

__global__ void hist_kernel(const float* __restrict__ pos) {
    int i = blockIdx.x * blockDim.x + threadIdx.x;
    if (i >= NPTS) return;
    int cx = cell_x(pos[i * 3 + 0]);
    int cy = cell_x(pos[i * 3 + 1]);
    int cz = cell_x(pos[i * 3 + 2]);
    atomicAdd(&g_count[(cz * NC + cy) * NC + cx], 1);
}

__global__ void scan_kernel() {
    __shared__ int s[NCELLS];
    int t = threadIdx.x;
    int v = g_count[t];
    s[t] = v;
    __syncthreads();
    for (int d = 1; d < NCELLS; d <<= 1) {
        int u = (t >= d) ? s[t - d] : 0;
        __syncthreads();
        s[t] += u;
        __syncthreads();
    }
    int excl = s[t] - v;
    g_start[t]  = excl;
    g_cursor[t] = excl;
    if (t == NCELLS - 1) g_start[NCELLS] = s[t];
}

__global__ void scatter_kernel(const float* __restrict__ pos) {
    int i = blockIdx.x * blockDim.x + threadIdx.x;
    if (i >= NPTS) return;
    float x = pos[i * 3 + 0];
    float y = pos[i * 3 + 1];
    float z = pos[i * 3 + 2];
    int c = (cell_x(z) * NC + cell_x(y)) * NC + cell_x(x);
    int slot = atomicAdd(&g_cursor[c], 1);
    g_spos[slot] = make_float4(x, y, z, __int_as_float(i));
}

__global__ void __launch_bounds__(TPB)
neigh_kernel(const float* __restrict__ pos,
             float* __restrict__ out_idx,   // [NPTS, MAXN] float32
             int* __restrict__ out_max)     // float32 bits, int atomicMax
{
    // per-warp bitset over all 8192 point indices: 256 words = 1KB, x8 warps = 8KB
    __shared__ unsigned bits[WPB][NPTS / 32];

    const int tid  = threadIdx.x;
    const int warp = tid >> 5;
    const int lane = tid & 31;
    const int row  = blockIdx.x * WPB + warp;

    // zero this warp's bitset
    #pragma unroll
    for (int t = 0; t < (NPTS / 32) / 32; t++)
        bits[warp][t * 32 + lane] = 0u;
    __syncwarp();

    const float px = pos[row * 3 + 0];
    const float py = pos[row * 3 + 1];
    const float pz = pos[row * 3 + 2];

    const int cx = cell_x(px), cy = cell_x(py), cz = cell_x(pz);
    const int cx0 = cx > 0 ? cx - 1 : 0, cx1 = cx < 7 ? cx + 1 : 7;
    const int cy0 = cy > 0 ? cy - 1 : 0, cy1 = cy < 7 ? cy + 1 : 7;
    const int cz0 = cz > 0 ? cz - 1 : 0, cz1 = cz < 7 ? cz + 1 : 7;

    // cx is the fastest-varying cell coordinate -> cx0..cx1 is one contiguous
    // range of the sorted array per (cy,cz): at most 9 ranges.
    for (int zz = cz0; zz <= cz1; zz++) {
        for (int yy = cy0; yy <= cy1; yy++) {
            const int base = (zz * NC + yy) * NC;
            const int s = g_start[base + cx0];
            const int e = g_start[base + cx1 + 1];
            for (int k = s + lane; k < e; k += 32) {
                const float4 q = g_spos[k];
                // exact left-to-right f32, no FMA (bit-matches reference mask)
                const float dx = __fsub_rn(q.x, px);
                const float dy = __fsub_rn(q.y, py);
                const float dz = __fsub_rn(q.z, pz);
                const float d2 = __fadd_rn(__fadd_rn(__fmul_rn(dx, dx),
                                                     __fmul_rn(dy, dy)),
                                           __fmul_rn(dz, dz));
                const int j = __float_as_int(q.w);
                if (d2 <= CUT2 && j != row)
                    atomicOr(&bits[warp][j >> 5], 1u << (j & 31));
            }
        }
    }
    __syncwarp();

    // Ordered emission: lane L owns words [L*8, L*8+8) (ascending index order).
    unsigned myw[8];
    int csum = 0;
    #pragma unroll
    for (int t = 0; t < 8; t++) {
        myw[t] = bits[warp][lane * 8 + t];
        csum += __popc(myw[t]);
    }
    // warp inclusive scan -> exclusive offset + total
    int x = csum;
    #pragma unroll
    for (int d = 1; d < 32; d <<= 1) {
        int v = __shfl_up_sync(0xffffffffu, x, d);
        if (lane >= d) x += v;
    }
    int off = x - csum;                               // exclusive prefix
    const int total = __shfl_sync(0xffffffffu, x, 31); // uncapped row count

    float* rowp = out_idx + (size_t)row * MAXN;
    #pragma unroll
    for (int t = 0; t < 8; t++) {
        unsigned m = myw[t];
        const int base = (lane * 8 + t) * 32;
        while (m) {
            const int b = __ffs(m) - 1;
            m &= m - 1;
            if (off < MAXN) rowp[off] = (float)(base + b);
            off++;
        }
    }

    // pad with -1.0f
    const int st = total < MAXN ? total : MAXN;
    for (int k = st + lane; k < MAXN; k += 32)
        rowp[k] = -1.0f;

    // global max of uncapped counts (float bits; non-negative -> int order == float order)
    if (lane == 0) atomicMax(out_max, __float_as_int((float)total));
}

extern "C" void kernel_launch(void* const* d_in, const int* in_sizes, int n_in,
                              void* d_out, int out_size)
{
    const float* pos = (const float*)d_in[0];
    float* out = (float*)d_out;

    const size_t toidx_elems = (size_t)NPTS * MAXN;      // 1,048,576
    const size_t cell_elems  = (size_t)NPTS * MAXN * 3;  // 3,145,728

    // zero cell_indices + max slot (0x0 == 0.0f)
    cudaMemsetAsync(out + toidx_elems, 0, (cell_elems + 1) * sizeof(float), 0);

    zero_kernel<<<1, NCELLS>>>();
    hist_kernel<<<NPTS / 256, 256>>>(pos);
    scan_kernel<<<1, NCELLS>>>();
    scatter_kernel<<<NPTS / 256, 256>>>(pos);
    neigh_kernel<<<NPTS / WPB, TPB>>>(
        pos, out, (int*)(out + toidx_elems + cell_elems));
}

// round 5
// speedup vs baseline: 2.6748x; 1.0395x over previous
#include <cuda_runtime.h>
#include <cuda_bf16.h>

#define NPTS 8192
#define MAXN 128
#define NC 8
#define NCELLS 512          // 8^3
#define CUT2 0.015625f      // 0.125^2, exact in fp32
#define WPB 8               // warps per block (main kernel)
#define TPB (WPB * 32)
#define PREP_T 1024
#define PPT (NPTS / PREP_T) // 8 points per prep thread

// Scratch (no allocations allowed)
__device__ int    g_start[NCELLS + 1];
__device__ float4 g_spos[NPTS];      // cell-sorted {x,y,z, idx-as-float-bits}

__device__ __forceinline__ int cell_x(float v) {
    // v in [0,1): v*8 is an exact exponent shift in fp32; trunc == floor.
    int c = (int)(v * 8.0f);
    return c < 0 ? 0 : (c > 7 ? 7 : c);
}

// ---------------- fused prep: hist + scan + scatter, one block ----------------
__global__ void __launch_bounds__(PREP_T)
prep_kernel(const float* __restrict__ pos)
{
    __shared__ int h[NCELLS];    // histogram, then reused as scatter cursor
    __shared__ int sc[NCELLS];   // inclusive scan

    const int t = threadIdx.x;
    if (t < NCELLS) h[t] = 0;
    __syncthreads();

    float4 p[PPT];
    int    c[PPT];
    #pragma unroll
    for (int k = 0; k < PPT; k++) {
        const int i = t + k * PREP_T;
        const float x = pos[3 * i + 0];
        const float y = pos[3 * i + 1];
        const float z = pos[3 * i + 2];
        c[k] = (cell_x(z) * NC + cell_x(y)) * NC + cell_x(x);
        p[k] = make_float4(x, y, z, __int_as_float(i));
        atomicAdd(&h[c[k]], 1);
    }
    __syncthreads();

    // Hillis-Steele inclusive scan over 512 cells (all threads hit barriers)
    const int v = (t < NCELLS) ? h[t] : 0;
    if (t < NCELLS) sc[t] = v;
    __syncthreads();
    for (int d = 1; d < NCELLS; d <<= 1) {
        const int u = (t < NCELLS && t >= d) ? sc[t - d] : 0;
        __syncthreads();
        if (t < NCELLS) sc[t] += u;
        __syncthreads();
    }
    if (t < NCELLS) {
        const int excl = sc[t] - v;
        g_start[t] = excl;
        h[t] = excl;                         // cursor
        if (t == NCELLS - 1) g_start[NCELLS] = sc[t];
    }
    __syncthreads();

    #pragma unroll
    for (int k = 0; k < PPT; k++) {
        const int slot = atomicAdd(&h[c[k]], 1);
        g_spos[slot] = p[k];
    }
}

// ---------------- main: warp per SORTED slot (spatial locality) ----------------
__global__ void __launch_bounds__(TPB)
neigh_kernel(float* __restrict__ out_idx,   // [NPTS, MAXN] float32
             int* __restrict__ out_max)     // float32 bits, int atomicMax
{
    // per-warp bitset over all 8192 point indices: 256 words = 1KB, x8 = 8KB
    __shared__ unsigned bits[WPB][NPTS / 32];

    const int tid  = threadIdx.x;
    const int warp = tid >> 5;
    const int lane = tid & 31;
    const int slot = blockIdx.x * WPB + warp;   // cell-sorted slot

    // zero this warp's bitset
    #pragma unroll
    for (int t = 0; t < (NPTS / 32) / 32; t++)
        bits[warp][t * 32 + lane] = 0u;
    __syncwarp();

    const float4 me = g_spos[slot];
    const float px = me.x, py = me.y, pz = me.z;
    const int   row = __float_as_int(me.w);

    const int cx = cell_x(px), cy = cell_x(py), cz = cell_x(pz);
    const int cx0 = cx > 0 ? cx - 1 : 0, cx1 = cx < 7 ? cx + 1 : 7;
    const int cy0 = cy > 0 ? cy - 1 : 0, cy1 = cy < 7 ? cy + 1 : 7;
    const int cz0 = cz > 0 ? cz - 1 : 0, cz1 = cz < 7 ? cz + 1 : 7;

    // cx fastest-varying -> cx0..cx1 contiguous in sorted array per (cy,cz)
    for (int zz = cz0; zz <= cz1; zz++) {
        for (int yy = cy0; yy <= cy1; yy++) {
            const int base = (zz * NC + yy) * NC;
            const int s = g_start[base + cx0];
            const int e = g_start[base + cx1 + 1];
            for (int k = s + lane; k < e; k += 32) {
                const float4 q = g_spos[k];
                // exact left-to-right f32, no FMA (bit-matches reference mask)
                const float dx = __fsub_rn(q.x, px);
                const float dy = __fsub_rn(q.y, py);
                const float dz = __fsub_rn(q.z, pz);
                const float d2 = __fadd_rn(__fadd_rn(__fmul_rn(dx, dx),
                                                     __fmul_rn(dy, dy)),
                                           __fmul_rn(dz, dz));
                const int j = __float_as_int(q.w);
                if (d2 <= CUT2 && j != row)
                    atomicOr(&bits[warp][j >> 5], 1u << (j & 31));
            }
        }
    }
    __syncwarp();

    // Ordered emission: lane L owns words [L*8, L*8+8) (ascending index order)
    unsigned myw[8];
    int csum = 0;
    #pragma unroll
    for (int t = 0; t < 8; t++) {
        myw[t] = bits[warp][lane * 8 + t];
        csum += __popc(myw[t]);
    }
    int x = csum;
    #pragma unroll
    for (int d = 1; d < 32; d <<= 1) {
        const int v = __shfl_up_sync(0xffffffffu, x, d);
        if (lane >= d) x += v;
    }
    int off = x - csum;                                // exclusive prefix
    const int total = __shfl_sync(0xffffffffu, x, 31); // uncapped count

    float* rowp = out_idx + (size_t)row * MAXN;
    #pragma unroll
    for (int t = 0; t < 8; t++) {
        unsigned m = myw[t];
        const int base = (lane * 8 + t) * 32;
        while (m) {
            const int b = __ffs(m) - 1;
            m &= m - 1;
            if (off < MAXN) rowp[off] = (float)(base + b);
            off++;
        }
    }

    // pad with -1.0f
    const int st = total < MAXN ? total : MAXN;
    for (int k = st + lane; k < MAXN; k += 32)
        rowp[k] = -1.0f;

    // global max of uncapped counts (non-negative float bits order as ints)
    if (lane == 0) atomicMax(out_max, __float_as_int((float)total));
}

extern "C" void kernel_launch(void* const* d_in, const int* in_sizes, int n_in,
                              void* d_out, int out_size)
{
    const float* pos = (const float*)d_in[0];
    float* out = (float*)d_out;

    const size_t toidx_elems = (size_t)NPTS * MAXN;      // 1,048,576
    const size_t cell_elems  = (size_t)NPTS * MAXN * 3;  // 3,145,728

    // zero cell_indices + max slot (0x0 == 0.0f)
    cudaMemsetAsync(out + toidx_elems, 0, (cell_elems + 1) * sizeof(float), 0);

    prep_kernel<<<1, PREP_T>>>(pos);
    neigh_kernel<<<NPTS / WPB, TPB>>>(
        out, (int*)(out + toidx_elems + cell_elems));
}

// round 6
// speedup vs baseline: 2.6857x; 1.0041x over previous
#include <cuda_runtime.h>
#include <cuda_bf16.h>

#define NPTS 8192
#define MAXN 128
#define NC 8
#define NCELLS 512          // 8^3
#define CUT2 0.015625f      // 0.125^2, exact in fp32
#define WPB 8               // warps per block (main kernel)
#define TPB (WPB * 32)
#define PREP_T 1024
#define PPT (NPTS / PREP_T) // 8 points per prep thread
#define LCAP 1024           // per-warp candidate list capacity

// Scratch (no allocations allowed)
__device__ int    g_start[NCELLS + 1];
__device__ float4 g_spos[NPTS];      // cell-sorted {x,y,z, idx-as-float-bits}

__device__ __forceinline__ int cell_x(float v) {
    // v in [0,1): v*8 is an exact exponent shift in fp32; trunc == floor.
    int c = (int)(v * 8.0f);
    return c < 0 ? 0 : (c > 7 ? 7 : c);
}

// ---------------- fused prep: hist + scan + scatter, one block ----------------
__global__ void __launch_bounds__(PREP_T)
prep_kernel(const float* __restrict__ pos, int* __restrict__ out_max)
{
    __shared__ int h[NCELLS];    // histogram, then reused as scatter cursor
    __shared__ int sc[NCELLS];   // inclusive scan

    const int t = threadIdx.x;
    if (t == 0) *out_max = 0;    // 0x0 == 0.0f; replaces the memset node
    if (t < NCELLS) h[t] = 0;
    __syncthreads();

    float4 p[PPT];
    int    c[PPT];
    #pragma unroll
    for (int k = 0; k < PPT; k++) {
        const int i = t + k * PREP_T;
        const float x = pos[3 * i + 0];
        const float y = pos[3 * i + 1];
        const float z = pos[3 * i + 2];
        c[k] = (cell_x(z) * NC + cell_x(y)) * NC + cell_x(x);
        p[k] = make_float4(x, y, z, __int_as_float(i));
        atomicAdd(&h[c[k]], 1);
    }
    __syncthreads();

    // Hillis-Steele inclusive scan over 512 cells
    const int v = (t < NCELLS) ? h[t] : 0;
    if (t < NCELLS) sc[t] = v;
    __syncthreads();
    for (int d = 1; d < NCELLS; d <<= 1) {
        const int u = (t < NCELLS && t >= d) ? sc[t - d] : 0;
        __syncthreads();
        if (t < NCELLS) sc[t] += u;
        __syncthreads();
    }
    if (t < NCELLS) {
        const int excl = sc[t] - v;
        g_start[t] = excl;
        h[t] = excl;                         // cursor
        if (t == NCELLS - 1) g_start[NCELLS] = sc[t];
    }
    __syncthreads();

    #pragma unroll
    for (int k = 0; k < PPT; k++) {
        const int slot = atomicAdd(&h[c[k]], 1);
        g_spos[slot] = p[k];
    }
}

// ---------------- main: warp per SORTED slot, flat candidate loop --------------
__global__ void __launch_bounds__(TPB)
neigh_kernel(float* __restrict__ out_idx,    // [NPTS, MAXN] float32
             float* __restrict__ out_cell,   // [NPTS, MAXN, 3] float32 (zeros)
             int* __restrict__ out_max)      // float32 bits, int atomicMax
{
    __shared__ unsigned bits[WPB][NPTS / 32];  // 8KB
    __shared__ int      list[WPB][LCAP];       // 32KB

    const int tid  = threadIdx.x;
    const int warp = tid >> 5;
    const int lane = tid & 31;
    const int slot = blockIdx.x * WPB + warp;   // cell-sorted slot

    // zero this warp's bitset
    #pragma unroll
    for (int t = 0; t < (NPTS / 32) / 32; t++)
        bits[warp][t * 32 + lane] = 0u;

    const float4 me = g_spos[slot];
    const float px = me.x, py = me.y, pz = me.z;
    const int   row = __float_as_int(me.w);

    // zero this row's cell_indices (replaces the memset node); 16B-aligned
    {
        float4* cp = (float4*)(out_cell + (size_t)row * (MAXN * 3));
        const float4 z4 = make_float4(0.f, 0.f, 0.f, 0.f);
        #pragma unroll
        for (int t = 0; t < 3; t++) cp[t * 32 + lane] = z4;
    }

    const int cx = cell_x(px), cy = cell_x(py), cz = cell_x(pz);
    const int cx0 = cx > 0 ? cx - 1 : 0, cx1 = cx < 7 ? cx + 1 : 7;

    // Fully-unrolled 3x3 (zz,yy) neighborhood: segment bounds in registers.
    // cx fastest-varying -> [cx0,cx1] contiguous in the sorted array.
    int T = 0;
    #pragma unroll
    for (int i = 0; i < 3; i++) {
        #pragma unroll
        for (int j = 0; j < 3; j++) {
            const int zz = cz - 1 + i;
            const int yy = cy - 1 + j;
            const bool val = (unsigned)zz < 8u && (unsigned)yy < 8u;
            const int base = val ? (zz * NC + yy) * NC : 0;
            const int s = g_start[base + cx0];
            const int e = val ? g_start[base + cx1 + 1] : s;
            const int len = e - s;
            // append candidate slots [s, e) to the per-warp list
            for (int k = lane; k < len; k += 32) {
                const int w = T + k;
                if (w < LCAP) list[warp][w] = s + k;
            }
            T += len;
        }
    }
    if (T > LCAP) T = LCAP;   // safety clamp (never hit for this data)
    __syncwarp();

    // Flat uniform loop: good unrolling + 4 LDG.128 in flight
    #pragma unroll 4
    for (int k = lane; k < T; k += 32) {
        const float4 q = g_spos[list[warp][k]];
        // exact left-to-right f32, no FMA (bit-matches reference mask)
        const float dx = __fsub_rn(q.x, px);
        const float dy = __fsub_rn(q.y, py);
        const float dz = __fsub_rn(q.z, pz);
        const float d2 = __fadd_rn(__fadd_rn(__fmul_rn(dx, dx),
                                             __fmul_rn(dy, dy)),
                                   __fmul_rn(dz, dz));
        const int j = __float_as_int(q.w);
        if (d2 <= CUT2 && j != row)
            atomicOr(&bits[warp][j >> 5], 1u << (j & 31));
    }
    __syncwarp();

    // Ordered emission: lane L owns words [L*8, L*8+8) (ascending index order)
    unsigned myw[8];
    int csum = 0;
    #pragma unroll
    for (int t = 0; t < 8; t++) {
        myw[t] = bits[warp][lane * 8 + t];
        csum += __popc(myw[t]);
    }
    int x = csum;
    #pragma unroll
    for (int d = 1; d < 32; d <<= 1) {
        const int v = __shfl_up_sync(0xffffffffu, x, d);
        if (lane >= d) x += v;
    }
    int off = x - csum;                                // exclusive prefix
    const int total = __shfl_sync(0xffffffffu, x, 31); // uncapped count

    float* rowp = out_idx + (size_t)row * MAXN;
    #pragma unroll
    for (int t = 0; t < 8; t++) {
        unsigned m = myw[t];
        const int base = (lane * 8 + t) * 32;
        while (m) {
            const int b = __ffs(m) - 1;
            m &= m - 1;
            if (off < MAXN) rowp[off] = (float)(base + b);
            off++;
        }
    }

    // pad with -1.0f
    const int st = total < MAXN ? total : MAXN;
    for (int k = st + lane; k < MAXN; k += 32)
        rowp[k] = -1.0f;

    // global max of uncapped counts (non-negative float bits order as ints)
    if (lane == 0) atomicMax(out_max, __float_as_int((float)total));
}

extern "C" void kernel_launch(void* const* d_in, const int* in_sizes, int n_in,
                              void* d_out, int out_size)
{
    const float* pos = (const float*)d_in[0];
    float* out = (float*)d_out;

    const size_t toidx_elems = (size_t)NPTS * MAXN;      // 1,048,576
    const size_t cell_elems  = (size_t)NPTS * MAXN * 3;  // 3,145,728

    int* out_max = (int*)(out + toidx_elems + cell_elems);

    prep_kernel<<<1, PREP_T>>>(pos, out_max);
    neigh_kernel<<<NPTS / WPB, TPB>>>(out, out + toidx_elems, out_max);
}

// round 7
// speedup vs baseline: 2.8602x; 1.0650x over previous
#include <cuda_runtime.h>
#include <cuda_bf16.h>

#define NPTS 8192
#define MAXN 128
#define NC 8
#define NCELLS 512          // 8^3
#define CUT2 0.015625f      // 0.125^2, exact in fp32
#define WPB 8               // warps per block (main kernel); 2 rows per warp
#define TPB (WPB * 32)
#define PREP_T 1024
#define PPT (NPTS / PREP_T)

// Scratch (no allocations allowed)
__device__ int    g_start[NCELLS + 1];
__device__ int    g_cursor[NCELLS];
__device__ float4 g_spos[NPTS];      // cell-sorted {x,y,z, idx-as-float-bits}

__device__ __forceinline__ int cell_x(float v) {
    // v in [0,1): v*8 is an exact exponent shift in fp32; trunc == floor.
    int c = (int)(v * 8.0f);
    return c < 0 ? 0 : (c > 7 ? 7 : c);
}

// -------- prep A: histogram + scan, one block (cheap part only) --------
__global__ void __launch_bounds__(PREP_T)
prep_hist_scan(const float* __restrict__ pos, int* __restrict__ out_max)
{
    __shared__ int h[NCELLS];
    __shared__ int sc[NCELLS];

    const int t = threadIdx.x;
    if (t == 0) *out_max = 0;            // 0x0 == 0.0f
    if (t < NCELLS) h[t] = 0;
    __syncthreads();

    #pragma unroll
    for (int k = 0; k < PPT; k++) {
        const int i = t + k * PREP_T;
        const int c = (cell_x(pos[3 * i + 2]) * NC + cell_x(pos[3 * i + 1])) * NC
                      + cell_x(pos[3 * i + 0]);
        atomicAdd(&h[c], 1);
    }
    __syncthreads();

    const int v = (t < NCELLS) ? h[t] : 0;
    if (t < NCELLS) sc[t] = v;
    __syncthreads();
    for (int d = 1; d < NCELLS; d <<= 1) {
        const int u = (t < NCELLS && t >= d) ? sc[t - d] : 0;
        __syncthreads();
        if (t < NCELLS) sc[t] += u;
        __syncthreads();
    }
    if (t < NCELLS) {
        const int excl = sc[t] - v;
        g_start[t]  = excl;
        g_cursor[t] = excl;
        if (t == NCELLS - 1) g_start[NCELLS] = sc[t];
    }
}

// -------- prep B: grid-wide scatter (parallelizes the store traffic) --------
__global__ void __launch_bounds__(256)
prep_scatter(const float* __restrict__ pos)
{
    const int i = blockIdx.x * 256 + threadIdx.x;
    const float x = pos[3 * i + 0];
    const float y = pos[3 * i + 1];
    const float z = pos[3 * i + 2];
    const int c = (cell_x(z) * NC + cell_x(y)) * NC + cell_x(x);
    const int slot = atomicAdd(&g_cursor[c], 1);
    g_spos[slot] = make_float4(x, y, z, __int_as_float(i));
}

// -------- main: warp per PAIR of sorted slots, direct segmented loop --------
__global__ void __launch_bounds__(TPB)
neigh_kernel(float* __restrict__ out_idx,    // [NPTS, MAXN] float32
             float* __restrict__ out_cell,   // [NPTS, MAXN, 3] float32 (zeros)
             int* __restrict__ out_max)      // float32 bits, int atomicMax
{
    __shared__ unsigned bits[WPB][2][NPTS / 32];   // 2KB per warp = 16KB

    const int warp = threadIdx.x >> 5;
    const int lane = threadIdx.x & 31;
    const int s0   = (blockIdx.x * WPB + warp) * 2;

    #pragma unroll
    for (int t = 0; t < 8; t++) {
        bits[warp][0][t * 32 + lane] = 0u;
        bits[warp][1][t * 32 + lane] = 0u;
    }

    const float4 A = g_spos[s0];
    const float4 B = g_spos[s0 + 1];
    const int rowA = __float_as_int(A.w);
    const int rowB = __float_as_int(B.w);

    // zero both rows' cell_indices (384 floats each, 16B-aligned)
    {
        float4* ca = (float4*)(out_cell + (size_t)rowA * (MAXN * 3));
        float4* cb = (float4*)(out_cell + (size_t)rowB * (MAXN * 3));
        const float4 z4 = make_float4(0.f, 0.f, 0.f, 0.f);
        #pragma unroll
        for (int t = 0; t < 3; t++) { ca[t * 32 + lane] = z4; cb[t * 32 + lane] = z4; }
    }

    const int cax = cell_x(A.x), cay = cell_x(A.y), caz = cell_x(A.z);
    const int cbx = cell_x(B.x), cby = cell_x(B.y), cbz = cell_x(B.z);
    __syncwarp();

    if (cax == cbx && cay == cby && caz == cbz) {
        // shared 27-neighborhood: one pass tests each candidate vs BOTH centers
        const int cx0 = cax > 0 ? cax - 1 : 0, cx1 = cax < 7 ? cax + 1 : 7;
        #pragma unroll
        for (int i = 0; i < 3; i++) {
            #pragma unroll
            for (int j2 = 0; j2 < 3; j2++) {
                const int zz = caz - 1 + i, yy = cay - 1 + j2;
                const bool val = (unsigned)zz < 8u && (unsigned)yy < 8u;
                const int base = val ? (zz * NC + yy) * NC : 0;
                const int s = g_start[base + cx0];
                const int e = val ? g_start[base + cx1 + 1] : s;
                for (int k = s + lane; k < e; k += 32) {
                    const float4 q = g_spos[k];
                    const int j = __float_as_int(q.w);
                    // exact left-to-right f32, no FMA (bit-matches reference)
                    const float axd = __fsub_rn(q.x, A.x);
                    const float ayd = __fsub_rn(q.y, A.y);
                    const float azd = __fsub_rn(q.z, A.z);
                    const float dA = __fadd_rn(__fadd_rn(__fmul_rn(axd, axd),
                                                         __fmul_rn(ayd, ayd)),
                                               __fmul_rn(azd, azd));
                    const float bxd = __fsub_rn(q.x, B.x);
                    const float byd = __fsub_rn(q.y, B.y);
                    const float bzd = __fsub_rn(q.z, B.z);
                    const float dB = __fadd_rn(__fadd_rn(__fmul_rn(bxd, bxd),
                                                         __fmul_rn(byd, byd)),
                                               __fmul_rn(bzd, bzd));
                    if (dA <= CUT2 && j != rowA)
                        atomicOr(&bits[warp][0][j >> 5], 1u << (j & 31));
                    if (dB <= CUT2 && j != rowB)
                        atomicOr(&bits[warp][1][j >> 5], 1u << (j & 31));
                }
            }
        }
    } else {
        // rare (~6%): pair straddles a cell boundary -> two single passes
        #pragma unroll
        for (int r = 0; r < 2; r++) {
            const float4 P = r ? B : A;
            const int row = r ? rowB : rowA;
            const int cx = r ? cbx : cax, cy = r ? cby : cay, cz = r ? cbz : caz;
            const int cx0 = cx > 0 ? cx - 1 : 0, cx1 = cx < 7 ? cx + 1 : 7;
            for (int i = 0; i < 3; i++) {
                for (int j2 = 0; j2 < 3; j2++) {
                    const int zz = cz - 1 + i, yy = cy - 1 + j2;
                    const bool val = (unsigned)zz < 8u && (unsigned)yy < 8u;
                    const int base = val ? (zz * NC + yy) * NC : 0;
                    const int s = g_start[base + cx0];
                    const int e = val ? g_start[base + cx1 + 1] : s;
                    for (int k = s + lane; k < e; k += 32) {
                        const float4 q = g_spos[k];
                        const int j = __float_as_int(q.w);
                        const float dx = __fsub_rn(q.x, P.x);
                        const float dy = __fsub_rn(q.y, P.y);
                        const float dz = __fsub_rn(q.z, P.z);
                        const float d2 = __fadd_rn(__fadd_rn(__fmul_rn(dx, dx),
                                                             __fmul_rn(dy, dy)),
                                                   __fmul_rn(dz, dz));
                        if (d2 <= CUT2 && j != row)
                            atomicOr(&bits[warp][r][j >> 5], 1u << (j & 31));
                    }
                }
            }
        }
    }
    __syncwarp();

    // Ordered emission for both rows
    #pragma unroll
    for (int r = 0; r < 2; r++) {
        const int row = r ? rowB : rowA;
        unsigned myw[8];
        int csum = 0;
        #pragma unroll
        for (int t = 0; t < 8; t++) {
            myw[t] = bits[warp][r][lane * 8 + t];
            csum += __popc(myw[t]);
        }
        int x = csum;
        #pragma unroll
        for (int d = 1; d < 32; d <<= 1) {
            const int v = __shfl_up_sync(0xffffffffu, x, d);
            if (lane >= d) x += v;
        }
        int off = x - csum;
        const int total = __shfl_sync(0xffffffffu, x, 31);

        float* rowp = out_idx + (size_t)row * MAXN;
        #pragma unroll
        for (int t = 0; t < 8; t++) {
            unsigned m = myw[t];
            const int base = (lane * 8 + t) * 32;
            while (m) {
                const int b = __ffs(m) - 1;
                m &= m - 1;
                if (off < MAXN) rowp[off] = (float)(base + b);
                off++;
            }
        }
        const int st = total < MAXN ? total : MAXN;
        for (int k = st + lane; k < MAXN; k += 32)
            rowp[k] = -1.0f;
        if (lane == 0) atomicMax(out_max, __float_as_int((float)total));
    }
}

extern "C" void kernel_launch(void* const* d_in, const int* in_sizes, int n_in,
                              void* d_out, int out_size)
{
    const float* pos = (const float*)d_in[0];
    float* out = (float*)d_out;

    const size_t toidx_elems = (size_t)NPTS * MAXN;      // 1,048,576
    const size_t cell_elems  = (size_t)NPTS * MAXN * 3;  // 3,145,728
    int* out_max = (int*)(out + toidx_elems + cell_elems);

    prep_hist_scan<<<1, PREP_T>>>(pos, out_max);
    prep_scatter<<<NPTS / 256, 256>>>(pos);
    neigh_kernel<<<NPTS / (2 * WPB), TPB>>>(out, out + toidx_elems, out_max);
}